// round 7
// baseline (speedup 1.0000x reference)
#include <cuda_runtime.h>
#include <float.h>

// Problem shape (fixed by the dataset)
#define BB    32
#define LL    8192
#define DD    256
#define TOPK  8
#define CHUNK 256
#define SS    (LL / CHUNK)     // 32 chunks along L
#define GRP   4                // row-groups per chunk (tid>>6)
#define SUB   (CHUNK / GRP)    // 64 rows per group

// Scratch (device globals: no allocation allowed anywhere)
__device__ float g_part[(size_t)BB * SS * DD * TOPK];  // 8.4 MB
__device__ int   g_nchunk[BB];                         // valid chunks per batch
__device__ int   g_cnt[BB];                            // completion tickets (self-resetting)

#define NEG (-FLT_MAX)

// Compare-exchange, descending (a keeps max). 2 FMNMX, no branches.
#define CE(a, b) { float _hi = fmaxf(a, b); float _lo = fminf(a, b); (a) = _hi; (b) = _lo; }

// Batcher odd-even sort-8, descending. 19 CE = 38 ops (optimal CE count).
__device__ __forceinline__ void sort8(float (&s)[8]) {
    CE(s[0], s[1]); CE(s[2], s[3]); CE(s[4], s[5]); CE(s[6], s[7]);
    CE(s[0], s[2]); CE(s[1], s[3]); CE(s[4], s[6]); CE(s[5], s[7]);
    CE(s[1], s[2]); CE(s[5], s[6]);
    CE(s[0], s[4]); CE(s[1], s[5]); CE(s[2], s[6]); CE(s[3], s[7]);
    CE(s[2], s[4]); CE(s[3], s[5]);
    CE(s[1], s[2]); CE(s[3], s[4]); CE(s[5], s[6]);
}

// Merge sorted-desc 8-list s into sorted-desc accumulator v (exact top-8 of
// the union). Partner stage (8 ops) + 3-stage bitonic merge-8 (24 ops).
__device__ __forceinline__ void acc8(float (&v)[8], const float (&s)[8]) {
    v[0] = fmaxf(v[0], s[7]); v[1] = fmaxf(v[1], s[6]);
    v[2] = fmaxf(v[2], s[5]); v[3] = fmaxf(v[3], s[4]);
    v[4] = fmaxf(v[4], s[3]); v[5] = fmaxf(v[5], s[2]);
    v[6] = fmaxf(v[6], s[1]); v[7] = fmaxf(v[7], s[0]);
    CE(v[0], v[4]); CE(v[1], v[5]); CE(v[2], v[6]); CE(v[3], v[7]);
    CE(v[0], v[2]); CE(v[1], v[3]); CE(v[4], v[6]); CE(v[5], v[7]);
    CE(v[0], v[1]); CE(v[2], v[3]); CE(v[4], v[5]); CE(v[6], v[7]);
}

// ---------------------------------------------------------------------------
// Single fused kernel. Block = (chunk s, batch b), 256 threads.
// Phase A (per-chunk top-8): q = tid&63 -> channels [4q,4q+4), g = tid>>6 ->
// rows [g*SUB,(g+1)*SUB) clipped by nvalid; 8-row sort8+acc8 batches; group
// results combined via smem; one sorted 8-list per (chunk,channel) to scratch.
// Phase B (fused merge): after a fenced scratch store each block takes a
// ticket; the holder of ticket nc-1 is the LAST storing block for batch b
// (tickets are unique, and the boundary block published g_nchunk[b] before
// its own fenced increment). That block merges the nc chunk-lists (thread d
// = channel d, scratch is L2-hot), writes the output, and resets the
// counter so graph replays start clean. Result is order-independent.
// ---------------------------------------------------------------------------
__global__ __launch_bounds__(256) void fused_kernel(const float* __restrict__ x,
                                                    const int* __restrict__ mask,
                                                    float* __restrict__ out) {
    __shared__ float sh[GRP][DD][TOPK + 1];   // +1 pad: conflict-free
    __shared__ int   wcnt[8];
    __shared__ int   s_ticket, s_nc;

    int b   = blockIdx.y;
    int s   = blockIdx.x;
    int tid = threadIdx.x;
    int q   = tid & 63;
    int g   = tid >> 6;
    int lo  = s * CHUNK;

    // nvalid for this chunk from its own mask rows (monotone 0...0 1...1)
    int m = mask[(size_t)b * LL + lo + tid];
    unsigned bal = __ballot_sync(0xffffffffu, m == 0);
    if ((tid & 31) == 0) wcnt[tid >> 5] = __popc(bal);
    __syncthreads();
    int nvalid = 0;
    #pragma unroll
    for (int w = 0; w < 8; ++w) nvalid += wcnt[w];

    // Publish the valid-chunk count: exactly one block per batch qualifies.
    if (tid == 0 && nvalid > 0) {
        bool last;
        if (nvalid < CHUNK)      last = true;
        else if (s == SS - 1)    last = true;
        else                     last = (mask[(size_t)b * LL + lo + CHUNK] == 1);
        if (last) g_nchunk[b] = s + 1;
    }
    if (nvalid == 0) return;   // never stored, never ticketed, never read

    int nv = min(max(nvalid - g * SUB, 0), SUB);
    int nfull = nv >> 3;
    int rem   = nv & 7;

    float v0[8], v1[8], v2[8], v3[8];
    #pragma unroll
    for (int j = 0; j < 8; ++j) { v0[j] = NEG; v1[j] = NEG; v2[j] = NEG; v3[j] = NEG; }

    const float4* p = reinterpret_cast<const float4*>(
                          x + ((size_t)b * LL + lo + g * SUB) * DD) + q;

    #pragma unroll 1
    for (int it = 0; it < nfull; ++it) {
        float4 r[8];
        #pragma unroll
        for (int j = 0; j < 8; ++j) r[j] = __ldcs(p + j * (DD / 4));
        p += 8 * (DD / 4);
        float t[8];
        #pragma unroll
        for (int j = 0; j < 8; ++j) t[j] = r[j].x;
        sort8(t); acc8(v0, t);
        #pragma unroll
        for (int j = 0; j < 8; ++j) t[j] = r[j].y;
        sort8(t); acc8(v1, t);
        #pragma unroll
        for (int j = 0; j < 8; ++j) t[j] = r[j].z;
        sort8(t); acc8(v2, t);
        #pragma unroll
        for (int j = 0; j < 8; ++j) t[j] = r[j].w;
        sort8(t); acc8(v3, t);
    }
    if (rem) {   // warp-uniform branch (g is uniform per warp)
        float4 r[8];
        #pragma unroll
        for (int j = 0; j < 8; ++j) r[j] = __ldcs(p + j * (DD / 4));  // in-bounds (within chunk)
        float t[8];
        #pragma unroll
        for (int j = 0; j < 8; ++j) t[j] = (j < rem) ? r[j].x : NEG;
        sort8(t); acc8(v0, t);
        #pragma unroll
        for (int j = 0; j < 8; ++j) t[j] = (j < rem) ? r[j].y : NEG;
        sort8(t); acc8(v1, t);
        #pragma unroll
        for (int j = 0; j < 8; ++j) t[j] = (j < rem) ? r[j].z : NEG;
        sort8(t); acc8(v2, t);
        #pragma unroll
        for (int j = 0; j < 8; ++j) t[j] = (j < rem) ? r[j].w : NEG;
        sort8(t); acc8(v3, t);
    }

    // combine the 4 row-groups per channel through smem
    #pragma unroll
    for (int j = 0; j < 8; ++j) sh[g][4 * q + 0][j] = v0[j];
    #pragma unroll
    for (int j = 0; j < 8; ++j) sh[g][4 * q + 1][j] = v1[j];
    #pragma unroll
    for (int j = 0; j < 8; ++j) sh[g][4 * q + 2][j] = v2[j];
    #pragma unroll
    for (int j = 0; j < 8; ++j) sh[g][4 * q + 3][j] = v3[j];
    __syncthreads();

    int d = tid;   // one channel per thread
    float v[8];
    #pragma unroll
    for (int j = 0; j < 8; ++j) v[j] = sh[0][d][j];
    #pragma unroll
    for (int gg = 1; gg < GRP; ++gg) {
        float t[8];
        #pragma unroll
        for (int j = 0; j < 8; ++j) t[j] = sh[gg][d][j];
        acc8(v, t);
    }
    float* dst = g_part + (((size_t)b * SS + s) * DD + d) * TOPK;
    #pragma unroll
    for (int j = 0; j < TOPK; ++j) dst[j] = v[j];   // 32B/thread, coalesced

    // ---- Phase B: last storing block for this batch merges everything ----
    __threadfence();   // scratch (and g_nchunk, for the boundary block) visible
    if (tid == 0) {
        int t = atomicAdd(&g_cnt[b], 1);
        __threadfence();                 // order the ticket before reading nc
        s_ticket = t;
        s_nc     = g_nchunk[b];
    }
    __syncthreads();
    int nc = s_nc;
    if (s_ticket != nc - 1) return;      // unique: only the last block passes

    // Merge nc sorted chunk-lists for channel d. Our own chunk s is already
    // in v; skip it. All other lists are recent writes -> L2-hot.
    const float* base = g_part + ((size_t)b * SS * DD + d) * TOPK;
    #pragma unroll 1
    for (int pp = 0; pp < nc; ++pp) {
        if (pp == s) continue;           // warp-uniform
        const float4* c4 = reinterpret_cast<const float4*>(base + (size_t)pp * DD * TOPK);
        float4 a = __ldg(c4);
        float4 e = __ldg(c4 + 1);
        float t[8] = {a.x, a.y, a.z, a.w, e.x, e.y, e.z, e.w};  // sorted desc
        acc8(v, t);
    }

    #pragma unroll
    for (int k = 0; k < TOPK; ++k)
        out[(size_t)b * TOPK * DD + (size_t)k * DD + d] = v[k];

    if (tid == 0) g_cnt[b] = 0;          // clean state for the next replay
}

extern "C" void kernel_launch(void* const* d_in, const int* in_sizes, int n_in,
                              void* d_out, int out_size) {
    const float* x    = (const float*)d_in[0];
    const int*   mask = (const int*)d_in[1];
    float*       out  = (float*)d_out;

    fused_kernel<<<dim3(SS, BB), 256>>>(x, mask, out);
}

// round 12
// speedup vs baseline: 1.0054x; 1.0054x over previous
#include <cuda_runtime.h>
#include <float.h>

// Problem shape (fixed by the dataset)
#define BB    32
#define LL    8192
#define DD    256
#define TOPK  8
#define CHUNK 256
#define SS    (LL / CHUNK)     // 32 chunks along L
#define GRP   2                // row-groups per chunk (tid>>7)
#define SUB   (CHUNK / GRP)    // 128 rows per group

// Scratch (device globals: no allocation allowed anywhere)
__device__ float g_part[(size_t)BB * SS * DD * TOPK];  // 8.4 MB
__device__ int   g_nchunk[BB];                         // valid chunks per batch

#define NEG (-FLT_MAX)

// Compare-exchange, descending (a keeps max). 2 FMNMX, no branches.
#define CE(a, b) { float _hi = fmaxf(a, b); float _lo = fminf(a, b); (a) = _hi; (b) = _lo; }

// Batcher odd-even sort-8, descending. 19 CE = 38 ops (optimal CE count).
__device__ __forceinline__ void sort8(float (&s)[8]) {
    CE(s[0], s[1]); CE(s[2], s[3]); CE(s[4], s[5]); CE(s[6], s[7]);
    CE(s[0], s[2]); CE(s[1], s[3]); CE(s[4], s[6]); CE(s[5], s[7]);
    CE(s[1], s[2]); CE(s[5], s[6]);
    CE(s[0], s[4]); CE(s[1], s[5]); CE(s[2], s[6]); CE(s[3], s[7]);
    CE(s[2], s[4]); CE(s[3], s[5]);
    CE(s[1], s[2]); CE(s[3], s[4]); CE(s[5], s[6]);
}

// Merge sorted-desc 8-list s into sorted-desc accumulator v (exact top-8 of
// the union). Partner stage (8 ops) + 3-stage bitonic merge-8 (24 ops).
__device__ __forceinline__ void acc8(float (&v)[8], const float (&s)[8]) {
    v[0] = fmaxf(v[0], s[7]); v[1] = fmaxf(v[1], s[6]);
    v[2] = fmaxf(v[2], s[5]); v[3] = fmaxf(v[3], s[4]);
    v[4] = fmaxf(v[4], s[3]); v[5] = fmaxf(v[5], s[2]);
    v[6] = fmaxf(v[6], s[1]); v[7] = fmaxf(v[7], s[0]);
    CE(v[0], v[4]); CE(v[1], v[5]); CE(v[2], v[6]); CE(v[3], v[7]);
    CE(v[0], v[2]); CE(v[1], v[3]); CE(v[4], v[6]); CE(v[5], v[7]);
    CE(v[0], v[1]); CE(v[2], v[3]); CE(v[4], v[5]); CE(v[6], v[7]);
}

// ---------------------------------------------------------------------------
// Kernel 1: per-chunk top-8. Block = (chunk s, batch b), 256 threads.
// q = tid&127 -> channels {2q, 2q+1} (float2 loads: warp reads 256B
// contiguous), g = tid>>7 -> rows [g*SUB,(g+1)*SUB) clipped by nvalid.
// 8-row batches: sort8 + acc8 (8.75 FMNMX/elem, family-optimal).
// Low register footprint (2 accum lists + 8 float2 loads) -> high occupancy.
// The unique boundary block publishes g_nchunk[b]; fully padded chunks exit
// without storing (merge never reads them).
// ---------------------------------------------------------------------------
__global__ __launch_bounds__(256) void partial_kernel(const float* __restrict__ x,
                                                      const int* __restrict__ mask) {
    __shared__ float sh[GRP][DD][TOPK + 1];   // +1 pad
    __shared__ int   wcnt[8];

    int b   = blockIdx.y;
    int s   = blockIdx.x;
    int tid = threadIdx.x;
    int q   = tid & 127;
    int g   = tid >> 7;
    int lo  = s * CHUNK;

    // nvalid for this chunk from its own mask rows (monotone 0...0 1...1)
    int m = mask[(size_t)b * LL + lo + tid];
    unsigned bal = __ballot_sync(0xffffffffu, m == 0);
    if ((tid & 31) == 0) wcnt[tid >> 5] = __popc(bal);
    __syncthreads();
    int nvalid = 0;
    #pragma unroll
    for (int w = 0; w < 8; ++w) nvalid += wcnt[w];

    // Publish the valid-chunk count: exactly one block per batch qualifies.
    if (tid == 0 && nvalid > 0) {
        bool last;
        if (nvalid < CHUNK)      last = true;
        else if (s == SS - 1)    last = true;
        else                     last = (mask[(size_t)b * LL + lo + CHUNK] == 1);
        if (last) g_nchunk[b] = s + 1;
    }
    if (nvalid == 0) return;   // merge never reads this chunk

    int nv = min(max(nvalid - g * SUB, 0), SUB);
    int nfull = nv >> 3;
    int rem   = nv & 7;

    float v0[8], v1[8];
    #pragma unroll
    for (int j = 0; j < 8; ++j) { v0[j] = NEG; v1[j] = NEG; }

    const float2* p = reinterpret_cast<const float2*>(
                          x + ((size_t)b * LL + lo + g * SUB) * DD) + q;

    #pragma unroll 1
    for (int it = 0; it < nfull; ++it) {
        float2 r[8];
        #pragma unroll
        for (int j = 0; j < 8; ++j) r[j] = __ldcs(p + j * (DD / 2));
        p += 8 * (DD / 2);
        float t[8];
        #pragma unroll
        for (int j = 0; j < 8; ++j) t[j] = r[j].x;
        sort8(t); acc8(v0, t);
        #pragma unroll
        for (int j = 0; j < 8; ++j) t[j] = r[j].y;
        sort8(t); acc8(v1, t);
    }
    if (rem) {   // warp-uniform branch (g uniform per warp)
        float2 r[8];
        #pragma unroll
        for (int j = 0; j < 8; ++j) r[j] = __ldcs(p + j * (DD / 2));  // in-bounds (within chunk)
        float t[8];
        #pragma unroll
        for (int j = 0; j < 8; ++j) t[j] = (j < rem) ? r[j].x : NEG;
        sort8(t); acc8(v0, t);
        #pragma unroll
        for (int j = 0; j < 8; ++j) t[j] = (j < rem) ? r[j].y : NEG;
        sort8(t); acc8(v1, t);
    }

    // combine the 2 row-groups per channel through smem
    #pragma unroll
    for (int j = 0; j < 8; ++j) sh[g][2 * q + 0][j] = v0[j];
    #pragma unroll
    for (int j = 0; j < 8; ++j) sh[g][2 * q + 1][j] = v1[j];
    __syncthreads();

    int d = tid;   // one channel per thread
    float v[8], t[8];
    #pragma unroll
    for (int j = 0; j < 8; ++j) v[j] = sh[0][d][j];
    #pragma unroll
    for (int j = 0; j < 8; ++j) t[j] = sh[1][d][j];
    acc8(v, t);

    float* dst = g_part + (((size_t)b * SS + s) * DD + d) * TOPK;
    #pragma unroll
    for (int j = 0; j < TOPK; ++j) dst[j] = v[j];   // 32B/thread, coalesced
}

// ---------------------------------------------------------------------------
// Kernel 2: merge the nc valid sorted chunk-lists per (b, d).
// Grid (BB, 8), 256 threads: c = tid&31 channel-in-group, seg = tid>>5 in
// [0,8). Segments split the nc valid chunks EVENLY (p0 = seg*nc/8) so every
// warp has work regardless of length. Segment results combined via smem.
// ---------------------------------------------------------------------------
__global__ __launch_bounds__(256) void merge_kernel(float* __restrict__ out) {
    __shared__ float sh[7][32][TOPK + 1];   // +1 pad
    int b   = blockIdx.x;
    int grp = blockIdx.y;                   // channel group of 32
    int c   = threadIdx.x & 31;
    int seg = threadIdx.x >> 5;             // 0..7
    int d   = grp * 32 + c;

    int nc = g_nchunk[b];                   // valid chunks, 1..32
    int p0 = (seg * nc) >> 3;
    int p1 = ((seg + 1) * nc) >> 3;

    const float* base = g_part + ((size_t)b * SS * DD + d) * TOPK;

    float v[8];
    #pragma unroll
    for (int j = 0; j < 8; ++j) v[j] = NEG;

    #pragma unroll 2
    for (int p = p0; p < p1; ++p) {
        const float4* c4 = reinterpret_cast<const float4*>(base + (size_t)p * DD * TOPK);
        float4 a = __ldg(c4);
        float4 e = __ldg(c4 + 1);
        float t[8] = {a.x, a.y, a.z, a.w, e.x, e.y, e.z, e.w};  // sorted desc
        acc8(v, t);
    }

    if (seg) {
        #pragma unroll
        for (int j = 0; j < 8; ++j) sh[seg - 1][c][j] = v[j];
    }
    __syncthreads();
    if (seg == 0) {
        #pragma unroll
        for (int ss = 0; ss < 7; ++ss) {
            float t[8];
            #pragma unroll
            for (int j = 0; j < 8; ++j) t[j] = sh[ss][c][j];
            acc8(v, t);
        }
        #pragma unroll
        for (int k = 0; k < TOPK; ++k)
            out[(size_t)b * TOPK * DD + (size_t)k * DD + d] = v[k];
    }
}

extern "C" void kernel_launch(void* const* d_in, const int* in_sizes, int n_in,
                              void* d_out, int out_size) {
    const float* x    = (const float*)d_in[0];
    const int*   mask = (const int*)d_in[1];
    float*       out  = (float*)d_out;

    partial_kernel<<<dim3(SS, BB), 256>>>(x, mask);
    merge_kernel<<<dim3(BB, 8), 256>>>(out);
}

// round 14
// speedup vs baseline: 1.1766x; 1.1703x over previous
#include <cuda_runtime.h>
#include <float.h>

// Problem shape (fixed by the dataset)
#define BB    32
#define LL    8192
#define DD    256
#define TOPK  8
#define CHUNK 256
#define SS    (LL / CHUNK)     // 32 chunks along L
#define GRP   4                // row-groups per chunk (tid>>6)
#define SUB   (CHUNK / GRP)    // 64 rows per group
#define MB    8                // merge blocks per batch

// Scratch (device globals: no allocation allowed anywhere)
__device__ float g_part[(size_t)BB * SS * DD * TOPK];  // 8.4 MB
__device__ int   g_nchunk[BB];  // valid chunks per batch (replay-invariant)
__device__ int   g_cnt[BB];     // stored-chunk arrivals (reset each replay)
__device__ int   g_done[BB];    // merge-block completion tickets (reset each replay)

#define NEG (-FLT_MAX)

// Compare-exchange, descending (a keeps max). 2 FMNMX, no branches.
#define CE(a, b) { float _hi = fmaxf(a, b); float _lo = fminf(a, b); (a) = _hi; (b) = _lo; }

// Batcher odd-even sort-8, descending. 19 CE = 38 ops (optimal CE count).
__device__ __forceinline__ void sort8(float (&s)[8]) {
    CE(s[0], s[1]); CE(s[2], s[3]); CE(s[4], s[5]); CE(s[6], s[7]);
    CE(s[0], s[2]); CE(s[1], s[3]); CE(s[4], s[6]); CE(s[5], s[7]);
    CE(s[1], s[2]); CE(s[5], s[6]);
    CE(s[0], s[4]); CE(s[1], s[5]); CE(s[2], s[6]); CE(s[3], s[7]);
    CE(s[2], s[4]); CE(s[3], s[5]);
    CE(s[1], s[2]); CE(s[3], s[4]); CE(s[5], s[6]);
}

// Merge sorted-desc 8-list s into sorted-desc accumulator v (exact top-8 of
// the union). Partner stage (8 ops) + 3-stage bitonic merge-8 (24 ops).
__device__ __forceinline__ void acc8(float (&v)[8], const float (&s)[8]) {
    v[0] = fmaxf(v[0], s[7]); v[1] = fmaxf(v[1], s[6]);
    v[2] = fmaxf(v[2], s[5]); v[3] = fmaxf(v[3], s[4]);
    v[4] = fmaxf(v[4], s[3]); v[5] = fmaxf(v[5], s[2]);
    v[6] = fmaxf(v[6], s[1]); v[7] = fmaxf(v[7], s[0]);
    CE(v[0], v[4]); CE(v[1], v[5]); CE(v[2], v[6]); CE(v[3], v[7]);
    CE(v[0], v[2]); CE(v[1], v[3]); CE(v[4], v[6]); CE(v[5], v[7]);
    CE(v[0], v[1]); CE(v[2], v[3]); CE(v[4], v[5]); CE(v[6], v[7]);
}

// ---------------------------------------------------------------------------
// Single kernel, grid (32, 40) x 256 threads.
//   y < BB : partial block (chunk s = x, batch b = y) — exact round-5 body.
//   y >= BB: merge block (batch b = x, channel group m = y-BB) — launches at
//            the END of the linear block order (y is the slow dimension), so
//            it never steals wave-1 slots from partials. Thread 0 spins until
//            its batch's chunk count is complete, then 8 segs merge the nc
//            chunk-lists for 32 channels and seg 0 writes the output.
// Sync protocol: storing partial blocks do {stores; threadfence; atomicAdd
// g_cnt[b]}. The boundary chunk publishes g_nchunk[b] BEFORE its fenced
// increment, so when g_cnt[b]==g_nchunk[b] all scratch is visible. Merge
// blocks ticket through g_done[b]; ticket MB-1 resets both counters so every
// graph replay starts clean (g_nchunk is replay-invariant; stale == correct).
// Deadlock-free: partial blocks never wait, so SM slots always free up.
// ---------------------------------------------------------------------------
__global__ __launch_bounds__(256) void topk_kernel(const float* __restrict__ x,
                                                   const int* __restrict__ mask,
                                                   float* __restrict__ out) {
    __shared__ float sh[GRP][DD][TOPK + 1];   // partial: group combine; merge: seg combine
    __shared__ int   wcnt[8];
    __shared__ int   s_nc;

    int tid = threadIdx.x;

    if (blockIdx.y >= BB) {
        // ---------------- merge block ----------------
        int b = blockIdx.x;
        int m = blockIdx.y - BB;            // channel group of 32
        int c = tid & 31;
        int seg = tid >> 5;                 // 0..7
        int d = m * 32 + c;

        if (tid == 0) {
            volatile int* vn = &g_nchunk[b];
            int nc;
            while ((nc = *vn) == 0) __nanosleep(64);
            while (atomicAdd(&g_cnt[b], 0) < nc) __nanosleep(64);
            s_nc = nc;
        }
        __syncthreads();
        __threadfence();                    // acquire: scratch stores visible
        int nc = s_nc;

        int p0 = (seg * nc) >> 3;
        int p1 = ((seg + 1) * nc) >> 3;
        const float* base = g_part + ((size_t)b * SS * DD + d) * TOPK;

        float v[8];
        #pragma unroll
        for (int j = 0; j < 8; ++j) v[j] = NEG;
        for (int p = p0; p < p1; ++p) {
            const float4* c4 = reinterpret_cast<const float4*>(base + (size_t)p * DD * TOPK);
            float4 a = __ldg(c4);
            float4 e = __ldg(c4 + 1);
            float t[8] = {a.x, a.y, a.z, a.w, e.x, e.y, e.z, e.w};  // sorted desc
            acc8(v, t);
        }

        float (*msh)[TOPK + 1] = reinterpret_cast<float(*)[TOPK + 1]>(&sh[0][0][0]);
        #pragma unroll
        for (int j = 0; j < 8; ++j) msh[seg * 32 + c][j] = v[j];
        __syncthreads();
        if (seg == 0) {
            #pragma unroll
            for (int s2 = 1; s2 < 8; ++s2) {
                float t[8];
                #pragma unroll
                for (int j = 0; j < 8; ++j) t[j] = msh[s2 * 32 + c][j];
                acc8(v, t);
            }
            #pragma unroll
            for (int k = 0; k < TOPK; ++k)
                out[(size_t)b * TOPK * DD + (size_t)k * DD + d] = v[k];
        }
        __syncthreads();
        if (tid == 0) {
            int t = atomicAdd(&g_done[b], 1);
            if (t == MB - 1) { g_cnt[b] = 0; g_done[b] = 0; }  // clean for replay
        }
        return;
    }

    // ---------------- partial block (round-5 body) ----------------
    int b   = blockIdx.y;
    int s   = blockIdx.x;
    int q   = tid & 63;
    int g   = tid >> 6;
    int lo  = s * CHUNK;

    // nvalid for this chunk from its own mask rows (monotone 0...0 1...1)
    int m = mask[(size_t)b * LL + lo + tid];
    unsigned bal = __ballot_sync(0xffffffffu, m == 0);
    if ((tid & 31) == 0) wcnt[tid >> 5] = __popc(bal);
    __syncthreads();
    int nvalid = 0;
    #pragma unroll
    for (int w = 0; w < 8; ++w) nvalid += wcnt[w];

    // Publish the valid-chunk count: exactly one block per batch qualifies.
    // Ordered before this block's fenced g_cnt increment below.
    if (tid == 0 && nvalid > 0) {
        bool last;
        if (nvalid < CHUNK)      last = true;
        else if (s == SS - 1)    last = true;
        else                     last = (mask[(size_t)b * LL + lo + CHUNK] == 1);
        if (last) g_nchunk[b] = s + 1;
    }
    if (nvalid == 0) return;   // never stores, never counted, never read

    int nv = min(max(nvalid - g * SUB, 0), SUB);
    int nfull = nv >> 3;
    int rem   = nv & 7;

    float v0[8], v1[8], v2[8], v3[8];
    #pragma unroll
    for (int j = 0; j < 8; ++j) { v0[j] = NEG; v1[j] = NEG; v2[j] = NEG; v3[j] = NEG; }

    const float4* p = reinterpret_cast<const float4*>(
                          x + ((size_t)b * LL + lo + g * SUB) * DD) + q;

    #pragma unroll 1
    for (int it = 0; it < nfull; ++it) {
        float4 r[8];
        #pragma unroll
        for (int j = 0; j < 8; ++j) r[j] = __ldcs(p + j * (DD / 4));
        p += 8 * (DD / 4);
        float t[8];
        #pragma unroll
        for (int j = 0; j < 8; ++j) t[j] = r[j].x;
        sort8(t); acc8(v0, t);
        #pragma unroll
        for (int j = 0; j < 8; ++j) t[j] = r[j].y;
        sort8(t); acc8(v1, t);
        #pragma unroll
        for (int j = 0; j < 8; ++j) t[j] = r[j].z;
        sort8(t); acc8(v2, t);
        #pragma unroll
        for (int j = 0; j < 8; ++j) t[j] = r[j].w;
        sort8(t); acc8(v3, t);
    }
    if (rem) {   // warp-uniform branch (g uniform per warp)
        float4 r[8];
        #pragma unroll
        for (int j = 0; j < 8; ++j) r[j] = __ldcs(p + j * (DD / 4));  // in-bounds (within chunk)
        float t[8];
        #pragma unroll
        for (int j = 0; j < 8; ++j) t[j] = (j < rem) ? r[j].x : NEG;
        sort8(t); acc8(v0, t);
        #pragma unroll
        for (int j = 0; j < 8; ++j) t[j] = (j < rem) ? r[j].y : NEG;
        sort8(t); acc8(v1, t);
        #pragma unroll
        for (int j = 0; j < 8; ++j) t[j] = (j < rem) ? r[j].z : NEG;
        sort8(t); acc8(v2, t);
        #pragma unroll
        for (int j = 0; j < 8; ++j) t[j] = (j < rem) ? r[j].w : NEG;
        sort8(t); acc8(v3, t);
    }

    // combine the 4 row-groups per channel through smem
    #pragma unroll
    for (int j = 0; j < 8; ++j) sh[g][4 * q + 0][j] = v0[j];
    #pragma unroll
    for (int j = 0; j < 8; ++j) sh[g][4 * q + 1][j] = v1[j];
    #pragma unroll
    for (int j = 0; j < 8; ++j) sh[g][4 * q + 2][j] = v2[j];
    #pragma unroll
    for (int j = 0; j < 8; ++j) sh[g][4 * q + 3][j] = v3[j];
    __syncthreads();

    int d = tid;   // one channel per thread
    float v[8];
    #pragma unroll
    for (int j = 0; j < 8; ++j) v[j] = sh[0][d][j];
    #pragma unroll
    for (int gg = 1; gg < GRP; ++gg) {
        float t[8];
        #pragma unroll
        for (int j = 0; j < 8; ++j) t[j] = sh[gg][d][j];
        acc8(v, t);
    }
    float* dst = g_part + (((size_t)b * SS + s) * DD + d) * TOPK;
    #pragma unroll
    for (int j = 0; j < TOPK; ++j) dst[j] = v[j];   // 32B/thread, coalesced

    // Release: scratch (and g_nchunk if we were the boundary block) visible
    // before the arrival counter ticks.
    __threadfence();
    __syncthreads();                 // all stores in this block issued
    if (tid == 0) atomicAdd(&g_cnt[b], 1);
}

extern "C" void kernel_launch(void* const* d_in, const int* in_sizes, int n_in,
                              void* d_out, int out_size) {
    const float* x    = (const float*)d_in[0];
    const int*   mask = (const int*)d_in[1];
    float*       out  = (float*)d_out;

    topk_kernel<<<dim3(SS, BB + MB), 256>>>(x, mask, out);
}